// round 16
// baseline (speedup 1.0000x reference)
#include <cuda_runtime.h>
#include <cuda_bf16.h>
#include <cuda_fp16.h>
#include <mma.h>
#include <cstdint>

using namespace nvcuda;

#define FDIM 128
#define SNEI 10
#define KCLU 16
#define NMAX 200704
#define BMAX 20480

typedef unsigned long long ull;

// scratch (__device__ globals per allocation rules)
__device__ float  g_pdot[NMAX];
__device__ float  g_c2[16];
__device__ __half g_prod[(size_t)NMAX * FDIM];
__device__ __half g_comb_h[(size_t)BMAX * 256];
__device__ __half g_comb_l[(size_t)BMAX * 256];
__device__ __half g_w_h[128 * 256];
__device__ unsigned char g_flag[NMAX];
__device__ int    g_list[NMAX];
__device__ int    g_count;

#define FFMA2(d, a, b, c) \
    asm("fma.rn.f32x2 %0, %1, %2, %3;" : "=l"(d) : "l"(a), "l"(b), "l"(c))
#define PACK2(d, lo, hi) \
    asm("mov.b64 %0, {%1, %2};" : "=l"(d) : "f"(lo), "f"(hi))
#define UNPACK2(lo, hi, v) \
    asm("mov.b64 {%0, %1}, %2;" : "=f"(lo), "=f"(hi) : "l"(v))

// ---------------------------------------------------------------------------
// prep: blocks 0..63 convert W to fp16; block 64 computes c2 + zero count;
// blocks 65..89 zero the flag array.
// ---------------------------------------------------------------------------
__global__ __launch_bounds__(512)
void prep_kernel(const float* __restrict__ w,
                 __half* __restrict__ wh,
                 const float* __restrict__ center,
                 float* __restrict__ c2,
                 unsigned char* __restrict__ flag,
                 int* __restrict__ count)
{
    if (blockIdx.x < 64) {
        int i = blockIdx.x * 512 + threadIdx.x;
        wh[i] = __float2half(w[i]);
    } else if (blockIdx.x == 64) {
        int wp = threadIdx.x >> 5, l = threadIdx.x & 31;
        float4 v = ((const float4*)center)[wp * 32 + l];
        float s = v.x * v.x + v.y * v.y + v.z * v.z + v.w * v.w;
#pragma unroll
        for (int o = 16; o; o >>= 1) s += __shfl_xor_sync(0xffffffffu, s, o);
        if (l == 0) c2[wp] = s;
        if (threadIdx.x == 0) *count = 0;
    } else {
        int i = (blockIdx.x - 65) * 512 + threadIdx.x;
        if (i < NMAX / 16)
            ((int4*)flag)[i] = make_int4(0, 0, 0, 0);
    }
}

// ---------------------------------------------------------------------------
// mark used nodes (plain byte stores; write-write races benign)
// ---------------------------------------------------------------------------
__global__ __launch_bounds__(256)
void flag_kernel(const int* __restrict__ neigh_idx,
                 unsigned char* __restrict__ flag, int total)
{
    int i = blockIdx.x * 256 + threadIdx.x;
    if (i < total) flag[neigh_idx[i]] = 1;
}

// ---------------------------------------------------------------------------
// compact used node ids into g_list (warp-aggregated atomics)
// ---------------------------------------------------------------------------
__global__ __launch_bounds__(256)
void compact_kernel(const unsigned char* __restrict__ flag,
                    int* __restrict__ list, int* __restrict__ count, int N)
{
    int i = blockIdx.x * 256 + threadIdx.x;
    bool used = (i < N) && flag[i];
    unsigned mask = __ballot_sync(0xffffffffu, used);
    int lane = threadIdx.x & 31;
    int cnt = __popc(mask);
    int pos = 0;
    if (lane == 0 && cnt) pos = atomicAdd(count, cnt);
    pos = __shfl_sync(0xffffffffu, pos, 0);
    if (used) list[pos + __popc(mask & ((1u << lane) - 1))] = i;
}

// ---------------------------------------------------------------------------
// Precompute per USED node: 64 list entries / block, 128 threads.
// Phase 2 ILP-2: thread (n, quarter h) processes nodes n and n+32, sharing
// every center/alpha broadcast load between the two FFMA2 streams.
// ---------------------------------------------------------------------------
#define RS4  132
#define QST  20

#define POFF_ROWS 0                        // 64*132*4 = 33792
#define POFF_CEN  33792                    // 16*128*4 = 8192
#define POFF_ALP  41984                    // 512
#define POFF_C2   42496                    // 64
#define POFF_Q    42560                    // 64*20*4  = 5120
#define POFF_PART 47680                    // 3*64*20*4 = 15360
#define POFF_NID  63040                    // 256
#define PSMB      63296

__global__ __launch_bounds__(128)
void precompute_kernel(const float* __restrict__ neigh_table,
                       const float* __restrict__ center,
                       const float* __restrict__ alpha,
                       const float* __restrict__ cmask,
                       const float* __restrict__ c2g,
                       const int* __restrict__ list,
                       const int* __restrict__ countp,
                       __half* __restrict__ prod,
                       float* __restrict__ pdot)
{
    extern __shared__ __align__(16) char smp[];
    float* rows_s = (float*)(smp + POFF_ROWS);
    float* cen_s  = (float*)(smp + POFF_CEN);
    float* alp_s  = (float*)(smp + POFF_ALP);
    float* c2_s   = (float*)(smp + POFF_C2);
    float* q_s    = (float*)(smp + POFF_Q);
    float* part_s = (float*)(smp + POFF_PART);   // [3][64][20]
    int*   nid_s  = (int*)(smp + POFF_NID);

    int count = *countp;
    int base = blockIdx.x * 64;
    if (base >= count) return;

    int t = threadIdx.x;
    int n = t & 31, h = t >> 5;          // node lane + quarter

    if (t < 64) nid_s[t] = (base + t < count) ? list[base + t] : 0;
    __syncthreads();

    ull mp[8];
#pragma unroll
    for (int kp = 0; kp < 8; kp++) {
        float m0 = cmask[(2 * kp) * FDIM + t];
        float m1 = cmask[(2 * kp + 1) * FDIM + t];
        PACK2(mp[kp], m0, m1);
    }

    // ---- stage 64 rows (via id table) + center + alpha + c2 ----
#pragma unroll
    for (int j = 0; j < 16; j++) {
        int i = j * 128 + t;
        int r = i >> 5, c = i & 31;
        float4 v = make_float4(0.f, 0.f, 0.f, 0.f);
        if (base + r < count)
            v = ((const float4*)neigh_table)[(size_t)nid_s[r] * 32 + c];
        *(float4*)&rows_s[r * RS4 + c * 4] = v;
    }
#pragma unroll
    for (int j = 0; j < 4; j++)
        ((float4*)cen_s)[j * 128 + t] = ((const float4*)center)[j * 128 + t];
    if (t < 32) ((float4*)alp_s)[t] = ((const float4*)alpha)[32 + t];
    if (t < 16) c2_s[t] = c2g[t];
    __syncthreads();

    // ---- phase 2: quarter-row reductions for TWO nodes per thread ----
    ull crA[16], crB[16], n2A = 0ull, n2B = 0ull, adA = 0ull, adB = 0ull;
#pragma unroll
    for (int k = 0; k < 16; k++) { crA[k] = 0ull; crB[k] = 0ull; }

    {
        const float4* rowA = (const float4*)&rows_s[n * RS4 + h * 32];
        const float4* rowB = (const float4*)&rows_s[(n + 32) * RS4 + h * 32];
#pragma unroll
        for (int q = 0; q < 8; q++) {
            float4 xa = rowA[q];
            float4 xb = rowB[q];
            ull xa0, xa1, xb0, xb1;
            PACK2(xa0, xa.x, xa.y);
            PACK2(xa1, xa.z, xa.w);
            PACK2(xb0, xb.x, xb.y);
            PACK2(xb1, xb.z, xb.w);
            ulonglong2 ap = ((const ulonglong2*)(alp_s + h * 32))[q];
            FFMA2(adA, xa0, ap.x, adA);
            FFMA2(adA, xa1, ap.y, adA);
            FFMA2(adB, xb0, ap.x, adB);
            FFMA2(adB, xb1, ap.y, adB);
            FFMA2(n2A, xa0, xa0, n2A);
            FFMA2(n2A, xa1, xa1, n2A);
            FFMA2(n2B, xb0, xb0, n2B);
            FFMA2(n2B, xb1, xb1, n2B);
#pragma unroll
            for (int k = 0; k < 16; k++) {
                ulonglong2 cp = ((const ulonglong2*)(cen_s + k * 128 + h * 32))[q];
                FFMA2(crA[k], xa0, cp.x, crA[k]);
                FFMA2(crA[k], xa1, cp.y, crA[k]);
                FFMA2(crB[k], xb0, cp.x, crB[k]);
                FFMA2(crB[k], xb1, cp.y, crB[k]);
            }
        }
    }

    float crAf[16], crBf[16], n2Av, n2Bv, adAv, adBv;
    {
        float lo, hi;
#pragma unroll
        for (int k = 0; k < 16; k++) {
            UNPACK2(lo, hi, crA[k]); crAf[k] = lo + hi;
            UNPACK2(lo, hi, crB[k]); crBf[k] = lo + hi;
        }
        UNPACK2(lo, hi, n2A); n2Av = lo + hi;
        UNPACK2(lo, hi, n2B); n2Bv = lo + hi;
        UNPACK2(lo, hi, adA); adAv = lo + hi;
        UNPACK2(lo, hi, adB); adBv = lo + hi;
    }

    // partials in dedicated region (no aliasing; single sync)
    if (h >= 1) {
        float* pA = &part_s[(h - 1) * 1280 + n * 20];
        float* pB = &part_s[(h - 1) * 1280 + (n + 32) * 20];
#pragma unroll
        for (int k = 0; k < 16; k++) { pA[k] = crAf[k]; pB[k] = crBf[k]; }
        pA[16] = n2Av; pA[17] = adAv;
        pB[16] = n2Bv; pB[17] = adBv;
    }
    __syncthreads();

    if (h == 0) {
        // node A = n
        {
            float n2t = n2Av, adt = adAv;
#pragma unroll
            for (int p = 0; p < 3; p++) {
                n2t += part_s[p * 1280 + n * 20 + 16];
                adt += part_s[p * 1280 + n * 20 + 17];
            }
            float bse = n2t + 1.0f;
#pragma unroll
            for (int k = 0; k < 16; k++) {
                float crt = crAf[k] + part_s[n * 20 + k]
                          + part_s[1280 + n * 20 + k]
                          + part_s[2560 + n * 20 + k];
                float den = fmaf(-2.0f, crt, bse + c2_s[k]);
                q_s[n * QST + k] = 1.0f / den;
            }
            if (base + n < count) pdot[nid_s[n]] = adt;
        }
        // node B = n + 32
        {
            int nb = n + 32;
            float n2t = n2Bv, adt = adBv;
#pragma unroll
            for (int p = 0; p < 3; p++) {
                n2t += part_s[p * 1280 + nb * 20 + 16];
                adt += part_s[p * 1280 + nb * 20 + 17];
            }
            float bse = n2t + 1.0f;
#pragma unroll
            for (int k = 0; k < 16; k++) {
                float crt = crBf[k] + part_s[nb * 20 + k]
                          + part_s[1280 + nb * 20 + k]
                          + part_s[2560 + nb * 20 + k];
                float den = fmaf(-2.0f, crt, bse + c2_s[k]);
                q_s[nb * QST + k] = 1.0f / den;
            }
            if (base + nb < count) pdot[nid_s[nb]] = adt;
        }
    }
    __syncthreads();

    // ---- phase 3: thread = feature t; loop 64 listed nodes ----
    int nlim = min(64, count - base);
    for (int nn = 0; nn < nlim; nn++) {
        const ulonglong2* qp2 = (const ulonglong2*)&q_s[nn * QST];
        ull acc = 0ull;
#pragma unroll
        for (int kp = 0; kp < 4; kp++) {
            ulonglong2 qq = qp2[kp];
            FFMA2(acc, qq.x, mp[2 * kp],     acc);
            FFMA2(acc, qq.y, mp[2 * kp + 1], acc);
        }
        float lo, hi; UNPACK2(lo, hi, acc);
        float x = rows_s[nn * RS4 + t];
        prod[(size_t)nid_s[nn] * FDIM + t] = __float2half(x * (lo + hi));
    }
}

// ---------------------------------------------------------------------------
// Row kernel: warp per row; gathers fp16 prod rows; emits fp16 hi/lo comb.
// (round-12 proven)
// ---------------------------------------------------------------------------
__global__ __launch_bounds__(256)
void row_kernel(const int* __restrict__ nodes,
                const int* __restrict__ neigh_idx,
                const float* __restrict__ self_table,
                const float* __restrict__ alpha,
                const float* __restrict__ pdot,
                const __half* __restrict__ prod,
                __half* __restrict__ comb_hi,
                __half* __restrict__ comb_lo,
                int B)
{
    int wid = threadIdx.x >> 5, lane = threadIdx.x & 31;
    int b = blockIdx.x * 8 + wid;
    if (b >= B) return;

    int node = nodes[b];
    int idx[SNEI];
#pragma unroll
    for (int s = 0; s < SNEI; s++) idx[s] = neigh_idx[b * SNEI + s];

    float4 sf = ((const float4*)self_table)[(size_t)node * 32 + lane];
    uint2 praw[SNEI];
#pragma unroll
    for (int s = 0; s < SNEI; s++)
        praw[s] = ((const uint2*)(prod + (size_t)idx[s] * FDIM))[lane];
    float pd[SNEI];
#pragma unroll
    for (int s = 0; s < SNEI; s++) pd[s] = pdot[idx[s]];

    float4 al = ((const float4*)alpha)[lane];
    float d = sf.x * al.x + sf.y * al.y + sf.z * al.z + sf.w * al.w;
#pragma unroll
    for (int o = 16; o; o >>= 1) d += __shfl_xor_sync(0xffffffffu, d, o);

    float e[SNEI], sum = 0.f;
#pragma unroll
    for (int s = 0; s < SNEI; s++) {
        float l = fmaxf(d + pd[s], 0.f);
        e[s] = __expf(l);
        sum += e[s];
    }
    float inv = 1.0f / sum;

    float4 agg = make_float4(0.f, 0.f, 0.f, 0.f);
#pragma unroll
    for (int s = 0; s < SNEI; s++) {
        float w = e[s] * inv;
        float2 f01 = __half22float2(*(const __half2*)&praw[s].x);
        float2 f23 = __half22float2(*(const __half2*)&praw[s].y);
        agg.x = fmaf(w, f01.x, agg.x);
        agg.y = fmaf(w, f01.y, agg.y);
        agg.z = fmaf(w, f23.x, agg.z);
        agg.w = fmaf(w, f23.y, agg.w);
    }

    float v[8] = {sf.x, sf.y, sf.z, sf.w, agg.x, agg.y, agg.z, agg.w};
    __half hh[8], ll[8];
#pragma unroll
    for (int i = 0; i < 8; i++) {
        hh[i] = __float2half(v[i]);
        ll[i] = __float2half(v[i] - __half2float(hh[i]));
    }
    __half2* ch = (__half2*)(comb_hi + (size_t)b * 256);
    __half2* cl = (__half2*)(comb_lo + (size_t)b * 256);
    ch[lane * 2]          = __halves2half2(hh[0], hh[1]);
    ch[lane * 2 + 1]      = __halves2half2(hh[2], hh[3]);
    ch[64 + lane * 2]     = __halves2half2(hh[4], hh[5]);
    ch[64 + lane * 2 + 1] = __halves2half2(hh[6], hh[7]);
    cl[lane * 2]          = __halves2half2(ll[0], ll[1]);
    cl[lane * 2 + 1]      = __halves2half2(ll[2], ll[3]);
    cl[64 + lane * 2]     = __halves2half2(ll[4], ll[5]);
    cl[64 + lane * 2 + 1] = __halves2half2(ll[6], ll[7]);
}

// ---------------------------------------------------------------------------
// fp16 wmma GEMM, 2 products: out = relu((Ah + Al) @ W16^T)  (round-12 proven)
// ---------------------------------------------------------------------------
#define GBM  64
#define GBK  64
#define AST  72
#define WST  72
#define A_CH (GBM * AST)
#define W_CH (128 * WST)
#define OFF_AH 0
#define OFF_AL (2 * A_CH)
#define OFF_W  (4 * A_CH)
#define GSMH   (OFF_W + 2 * W_CH)

__global__ __launch_bounds__(256, 2)
void gemm_wmma_kernel(const __half* __restrict__ Ah,
                      const __half* __restrict__ Al,
                      const __half* __restrict__ W16,
                      float* __restrict__ out,
                      int Brows)
{
    extern __shared__ __align__(16) __half smg[];
    __half* Ahs = smg + OFF_AH;
    __half* Als = smg + OFF_AL;
    __half* Ws  = smg + OFF_W;

    int tid = threadIdx.x;
    int w = tid >> 5;
    int wm = w & 1, wn = w >> 1;
    int row0 = blockIdx.x * GBM;
    int m0 = wm * 32, n0 = wn * 32;

    wmma::fragment<wmma::accumulator, 16, 16, 16, float> acc[2][2];
#pragma unroll
    for (int i = 0; i < 2; i++)
#pragma unroll
        for (int j = 0; j < 2; j++)
            wmma::fill_fragment(acc[i][j], 0.0f);

    uint4 pah[2], pal[2], pw[4];

#pragma unroll
    for (int j = 0; j < 2; j++) {
        int i = j * 256 + tid;
        int r = i >> 3, c8 = (i & 7) * 8;
        pah[j] = make_uint4(0, 0, 0, 0);
        pal[j] = make_uint4(0, 0, 0, 0);
        if (row0 + r < Brows) {
            pah[j] = *(const uint4*)&Ah[(size_t)(row0 + r) * 256 + c8];
            pal[j] = *(const uint4*)&Al[(size_t)(row0 + r) * 256 + c8];
        }
    }
#pragma unroll
    for (int j = 0; j < 4; j++) {
        int i = j * 256 + tid;
        int r = i >> 3, c8 = (i & 7) * 8;
        pw[j] = *(const uint4*)&W16[(size_t)r * 256 + c8];
    }
#pragma unroll
    for (int j = 0; j < 2; j++) {
        int i = j * 256 + tid;
        int r = i >> 3, c8 = (i & 7) * 8;
        *(uint4*)&Ahs[r * AST + c8] = pah[j];
        *(uint4*)&Als[r * AST + c8] = pal[j];
    }
#pragma unroll
    for (int j = 0; j < 4; j++) {
        int i = j * 256 + tid;
        int r = i >> 3, c8 = (i & 7) * 8;
        *(uint4*)&Ws[r * WST + c8] = pw[j];
    }
    __syncthreads();

    int buf = 0;
#pragma unroll
    for (int chunk = 0; chunk < 4; chunk++) {
        if (chunk < 3) {
            int kc = (chunk + 1) * GBK;
#pragma unroll
            for (int j = 0; j < 2; j++) {
                int i = j * 256 + tid;
                int r = i >> 3, c8 = (i & 7) * 8;
                pah[j] = make_uint4(0, 0, 0, 0);
                pal[j] = make_uint4(0, 0, 0, 0);
                if (row0 + r < Brows) {
                    pah[j] = *(const uint4*)&Ah[(size_t)(row0 + r) * 256 + kc + c8];
                    pal[j] = *(const uint4*)&Al[(size_t)(row0 + r) * 256 + kc + c8];
                }
            }
#pragma unroll
            for (int j = 0; j < 4; j++) {
                int i = j * 256 + tid;
                int r = i >> 3, c8 = (i & 7) * 8;
                pw[j] = *(const uint4*)&W16[(size_t)r * 256 + kc + c8];
            }
        }

        const __half* Ab_h = Ahs + buf * A_CH;
        const __half* Ab_l = Als + buf * A_CH;
        const __half* Wb   = Ws  + buf * W_CH;
#pragma unroll
        for (int kk = 0; kk < GBK; kk += 16) {
            wmma::fragment<wmma::matrix_a, 16, 16, 16, __half, wmma::row_major> fah[2], fal[2];
            wmma::fragment<wmma::matrix_b, 16, 16, 16, __half, wmma::col_major> fb[2];
#pragma unroll
            for (int i = 0; i < 2; i++) {
                wmma::load_matrix_sync(fah[i], &Ab_h[(m0 + i * 16) * AST + kk], AST);
                wmma::load_matrix_sync(fal[i], &Ab_l[(m0 + i * 16) * AST + kk], AST);
            }
#pragma unroll
            for (int j = 0; j < 2; j++)
                wmma::load_matrix_sync(fb[j], &Wb[(n0 + j * 16) * WST + kk], WST);
#pragma unroll
            for (int i = 0; i < 2; i++)
#pragma unroll
                for (int j = 0; j < 2; j++) {
                    wmma::mma_sync(acc[i][j], fah[i], fb[j], acc[i][j]);
                    wmma::mma_sync(acc[i][j], fal[i], fb[j], acc[i][j]);
                }
        }

        if (chunk < 3) {
            int nb = buf ^ 1;
            __syncthreads();
#pragma unroll
            for (int j = 0; j < 2; j++) {
                int i = j * 256 + tid;
                int r = i >> 3, c8 = (i & 7) * 8;
                *(uint4*)&Ahs[nb * A_CH + r * AST + c8] = pah[j];
                *(uint4*)&Als[nb * A_CH + r * AST + c8] = pal[j];
            }
#pragma unroll
            for (int j = 0; j < 4; j++) {
                int i = j * 256 + tid;
                int r = i >> 3, c8 = (i & 7) * 8;
                *(uint4*)&Ws[nb * W_CH + r * WST + c8] = pw[j];
            }
            __syncthreads();
            buf = nb;
        }
    }

#pragma unroll
    for (int i = 0; i < 2; i++) {
        int gr = row0 + m0 + i * 16;
        if (gr < Brows) {
#pragma unroll
            for (int j = 0; j < 2; j++) {
#pragma unroll
                for (int e = 0; e < acc[i][j].num_elements; e++)
                    acc[i][j].x[e] = fmaxf(acc[i][j].x[e], 0.0f);
                wmma::store_matrix_sync(&out[(size_t)gr * FDIM + n0 + j * 16],
                                        acc[i][j], FDIM, wmma::mem_row_major);
            }
        }
    }
}

// ---------------------------------------------------------------------------
extern "C" void kernel_launch(void* const* d_in, const int* in_sizes, int n_in,
                              void* d_out, int out_size)
{
    const int*   nodes      = (const int*)d_in[0];
    const int*   neigh_idx  = (const int*)d_in[1];
    const float* self_table = (const float*)d_in[2];
    const float* neigh_tab  = (const float*)d_in[3];
    const float* center     = (const float*)d_in[4];
    const float* cmask      = (const float*)d_in[5];
    const float* weight     = (const float*)d_in[6];
    const float* alpha      = (const float*)d_in[7];
    float*       out        = (float*)d_out;

    int B = in_sizes[0];
    int N = in_sizes[3] / FDIM;
    int totalNeigh = in_sizes[1];

    float *pd, *c2;
    __half *prod, *ch, *cl, *wh;
    unsigned char* flag;
    int *list, *count;
    cudaGetSymbolAddress((void**)&prod,  g_prod);
    cudaGetSymbolAddress((void**)&pd,    g_pdot);
    cudaGetSymbolAddress((void**)&c2,    g_c2);
    cudaGetSymbolAddress((void**)&ch,    g_comb_h);
    cudaGetSymbolAddress((void**)&cl,    g_comb_l);
    cudaGetSymbolAddress((void**)&wh,    g_w_h);
    cudaGetSymbolAddress((void**)&flag,  g_flag);
    cudaGetSymbolAddress((void**)&list,  g_list);
    cudaGetSymbolAddress((void**)&count, g_count);

    cudaFuncSetAttribute(precompute_kernel,
                         cudaFuncAttributeMaxDynamicSharedMemorySize, PSMB);
    cudaFuncSetAttribute(gemm_wmma_kernel,
                         cudaFuncAttributeMaxDynamicSharedMemorySize,
                         GSMH * (int)sizeof(__half));

    prep_kernel<<<90, 512>>>(weight, wh, center, c2, flag, count);
    flag_kernel<<<(totalNeigh + 255) / 256, 256>>>(neigh_idx, flag, totalNeigh);
    compact_kernel<<<(N + 255) / 256, 256>>>(flag, list, count, N);
    precompute_kernel<<<(N + 63) / 64, 128, PSMB>>>(neigh_tab, center, alpha,
                                                    cmask, c2, list, count,
                                                    prod, pd);
    row_kernel<<<(B + 7) / 8, 256>>>(nodes, neigh_idx, self_table, alpha,
                                     pd, prod, ch, cl, B);
    gemm_wmma_kernel<<<(B + GBM - 1) / GBM, 256,
                      GSMH * (int)sizeof(__half)>>>(ch, cl, wh, out, B);
}